// round 12
// baseline (speedup 1.0000x reference)
#include <cuda_runtime.h>
#include <cuda_bf16.h>
#include <cuda_fp16.h>
#include <cstdint>
#include <math.h>

#define NB 4
#define T 4096
#define NH 16
#define DH 128
#define DV 128
#define CHUNK 1024
#define NCK 4
#define HALFD 64
#define LOG2E 1.4426950408889634f
#define NEGBIG -1e30f

#define TB2 32768                     // 128 rows x 256B, XOR-swizzled tile
#define NTILES (NB * NH * NCK * 8)    // 2048

// ---------------- device scratch (no cudaMalloc allowed) -------------------
__device__ __align__(128) uint8_t g_khi[(size_t)NTILES * TB2];
__device__ __align__(128) uint8_t g_klo[(size_t)NTILES * TB2];
__device__ __align__(128) uint8_t g_vt [(size_t)NTILES * TB2];
__device__ float   g_cos[T * HALFD];
__device__ float   g_sin[T * HALFD];

// ---------------- helpers ---------------------------------------------------
__device__ __forceinline__ uint32_t smem_u32(const void* p) {
    uint32_t a;
    asm("{ .reg .u64 t; cvta.to.shared.u64 t, %1; cvt.u32.u64 %0, t; }"
        : "=r"(a) : "l"(p));
    return a;
}

__device__ __forceinline__ uint32_t elect_one() {
    uint32_t p;
    asm volatile("{ .reg .pred p; elect.sync _|p, 0xFFFFFFFF; selp.b32 %0, 1, 0, p; }"
                 : "=r"(p));
    return p;
}

__device__ __forceinline__ float ex2(float x) {
    float y;
    asm("ex2.approx.ftz.f32 %0, %1;" : "=f"(y) : "f"(x));
    return y;
}

__device__ __forceinline__ uint32_t h2ex2(uint32_t x) {
    uint32_t y;
    asm("ex2.approx.f16x2 %0, %1;" : "=r"(y) : "r"(x));
    return y;
}

__device__ __forceinline__ uint32_t f2h2(float a, float b) {
    uint32_t y;
    asm("cvt.rn.f16x2.f32 %0, %2, %1;" : "=r"(y) : "f"(a), "f"(b));
    return y;
}

__device__ __forceinline__ uint32_t bf2u(__nv_bfloat16 a, __nv_bfloat16 b) {
    __nv_bfloat162 t = __halves2bfloat162(a, b);
    return *reinterpret_cast<uint32_t*>(&t);
}

// swizzled tile layout: elem (r, c) 2B: 256B row stride, 16B chunk ^= (r&7)
__device__ __forceinline__ uint32_t toff(int r, int c) {
    return (uint32_t)(r * 256 + ((((c >> 3) ^ (r & 7))) << 4) + (c & 7) * 2);
}

__device__ __forceinline__ void split_store(uint8_t* hi, uint8_t* lo, int r, int kd, float4 v) {
    __nv_bfloat16 h0 = __float2bfloat16_rn(v.x);
    __nv_bfloat16 h1 = __float2bfloat16_rn(v.y);
    __nv_bfloat16 h2 = __float2bfloat16_rn(v.z);
    __nv_bfloat16 h3 = __float2bfloat16_rn(v.w);
    __nv_bfloat16 l0 = __float2bfloat16_rn(v.x - __bfloat162float(h0));
    __nv_bfloat16 l1 = __float2bfloat16_rn(v.y - __bfloat162float(h1));
    __nv_bfloat16 l2 = __float2bfloat16_rn(v.z - __bfloat162float(h2));
    __nv_bfloat16 l3 = __float2bfloat16_rn(v.w - __bfloat162float(h3));
    uint32_t off = toff(r, kd);
    *reinterpret_cast<uint2*>(hi + off) = make_uint2(bf2u(h0, h1), bf2u(h2, h3));
    *reinterpret_cast<uint2*>(lo + off) = make_uint2(bf2u(l0, l1), bf2u(l2, l3));
}

// ---------------- mbarrier / bulk copy (sm_90 baseline) ---------------------
#define MBAR_INIT(mb, n) \
    asm volatile("mbarrier.init.shared.b64 [%0], %1;" :: "r"(mb), "r"((uint32_t)(n)) : "memory")
#define MBAR_EXPECT_TX(mb, bytes) \
    asm volatile("mbarrier.arrive.expect_tx.shared.b64 _, [%0], %1;" \
                 :: "r"(mb), "r"((uint32_t)(bytes)) : "memory")

__device__ __forceinline__ void mbar_wait(uint32_t mb, uint32_t phase) {
    asm volatile(
        "{\n\t.reg .pred P;\n\t"
        "LAB_W%=:\n\t"
        "mbarrier.try_wait.parity.acquire.cta.shared::cta.b64 P, [%0], %1, 0x989680;\n\t"
        "@P bra.uni LAB_D%=;\n\t"
        "bra.uni LAB_W%=;\n\t"
        "LAB_D%=:\n\t}"
        :: "r"(mb), "r"(phase) : "memory");
}

__device__ __forceinline__ void bulk_g2s(uint32_t dst, const void* src, uint32_t bytes, uint32_t mb) {
    asm volatile(
        "cp.async.bulk.shared::cluster.global.mbarrier::complete_tx::bytes [%0], [%1], %2, [%3];"
        :: "r"(dst), "l"(src), "r"(bytes), "r"(mb) : "memory");
}

#define BAR_ARRIVE(id) asm volatile("bar.arrive %0, 256;" :: "r"(id) : "memory")
#define BAR_SYNC(id)   asm volatile("bar.sync %0, 256;" :: "r"(id) : "memory")

// ---------------- mma.sync + ldmatrix ---------------------------------------
__device__ __forceinline__ void ldsm4(uint32_t* r, uint32_t addr) {
    asm volatile("ldmatrix.sync.aligned.m8n8.x4.shared.b16 {%0,%1,%2,%3}, [%4];"
                 : "=r"(r[0]), "=r"(r[1]), "=r"(r[2]), "=r"(r[3]) : "r"(addr));
}

__device__ __forceinline__ void mma_bf16(float* c, const uint32_t* a, uint32_t b0, uint32_t b1) {
    asm volatile(
        "mma.sync.aligned.m16n8k16.row.col.f32.bf16.bf16.f32 "
        "{%0,%1,%2,%3}, {%4,%5,%6,%7}, {%8,%9}, {%0,%1,%2,%3};"
        : "+f"(c[0]), "+f"(c[1]), "+f"(c[2]), "+f"(c[3])
        : "r"(a[0]), "r"(a[1]), "r"(a[2]), "r"(a[3]), "r"(b0), "r"(b1));
}

__device__ __forceinline__ void mma_f16(float* c, const uint32_t* a, uint32_t b0, uint32_t b1) {
    asm volatile(
        "mma.sync.aligned.m16n8k16.row.col.f32.f16.f16.f32 "
        "{%0,%1,%2,%3}, {%4,%5,%6,%7}, {%8,%9}, {%0,%1,%2,%3};"
        : "+f"(c[0]), "+f"(c[1]), "+f"(c[2]), "+f"(c[3])
        : "r"(a[0]), "r"(a[1]), "r"(a[2]), "r"(a[3]), "r"(b0), "r"(b1));
}

// ---------------- prep kernels ----------------------------------------------
__global__ void tables_kernel(const int* __restrict__ startp) {
    __shared__ float invf_s[HALFD];
    int tid = threadIdx.x;
    if (tid < HALFD) {
        double invf = exp(-(double)tid * (log(10000.0) / (double)HALFD));
        invf_s[tid] = (float)invf;
    }
    __syncthreads();
    int idx = blockIdx.x * blockDim.x + tid;
    if (idx >= T * HALFD) return;
    int t = idx >> 6, i = idx & 63;
    float ang = (float)(*startp + t) * invf_s[i];
    float s, c;
    sincosf(ang, &s, &c);
    g_cos[idx] = c;
    g_sin[idx] = s;
}

// block-per-tile: build hi/lo tile images in SMEM, stream out coalesced
__global__ __launch_bounds__(256) void kprep_kernel(const float* __restrict__ k) {
    extern __shared__ __align__(16) uint8_t kim[];
    uint8_t* hi = kim;
    uint8_t* lo = kim + TB2;
    int tix = blockIdx.x;
    int j = tix & 7, c = (tix >> 3) & 3, h = (tix >> 5) & 15, b = tix >> 9;
    int tid = threadIdx.x;

#pragma unroll
    for (int p = 0; p < 8; ++p) {
        int u = tid + p * 256;
        int r = u >> 4, i = u & 15;
        int t = c * 1024 + j * 128 + r;
        const float* kr = k + ((size_t)(b * T + t) * NH + h) * DH;
        float4 x1 = *reinterpret_cast<const float4*>(kr + 4 * i);
        float4 x2 = *reinterpret_cast<const float4*>(kr + 64 + 4 * i);
        float4 cc = *reinterpret_cast<const float4*>(g_cos + t * HALFD + 4 * i);
        float4 ss = *reinterpret_cast<const float4*>(g_sin + t * HALFD + 4 * i);
        float4 r1 = make_float4(x1.x * cc.x - x2.x * ss.x, x1.y * cc.y - x2.y * ss.y,
                                x1.z * cc.z - x2.z * ss.z, x1.w * cc.w - x2.w * ss.w);
        float4 r2 = make_float4(x2.x * cc.x + x1.x * ss.x, x2.y * cc.y + x1.y * ss.y,
                                x2.z * cc.z + x1.z * ss.z, x2.w * cc.w + x1.w * ss.w);
        split_store(hi, lo, r, 4 * i, r1);
        split_store(hi, lo, r, 64 + 4 * i, r2);
    }
    __syncthreads();

    size_t tb = (size_t)tix * TB2;
    uint4* dh = reinterpret_cast<uint4*>(g_khi + tb);
    uint4* dl = reinterpret_cast<uint4*>(g_klo + tb);
    const uint4* sh = reinterpret_cast<const uint4*>(hi);
    const uint4* sl = reinterpret_cast<const uint4*>(lo);
    for (int e = tid; e < TB2 / 16; e += 256) {
        dh[e] = sh[e];
        dl[e] = sl[e];
    }
}

// V -> V^T tiles [dv][kpos] as f16, swizzled 256B-stride layout
__global__ __launch_bounds__(256) void vprep_kernel(const float* __restrict__ v) {
    __shared__ __half st[128 * 130];
    int tix = blockIdx.x;
    int j = tix & 7, c = (tix >> 3) & 3, h = (tix >> 5) & 15, b = tix >> 9;
    int t0 = c * 1024 + j * 128;
    for (int e = threadIdx.x; e < 16384; e += 256) {
        int kl = e >> 7, dv = e & 127;
        float val = v[((size_t)(b * T + t0 + kl) * NH + h) * DV + dv];
        st[dv * 130 + kl] = __float2half_rn(val);
    }
    __syncthreads();
    uint8_t* dst = g_vt + (size_t)tix * TB2;
    for (int e = threadIdx.x; e < 2048; e += 256) {
        int dv = e >> 4, ch = e & 15;
        const uint32_t* s = reinterpret_cast<const uint32_t*>(&st[dv * 130 + ch * 8]);
        uint4 w = make_uint4(s[0], s[1], s[2], s[3]);
        *reinterpret_cast<uint4*>(dst + (uint32_t)(dv * 256 + ((ch ^ (dv & 7)) << 4))) = w;
    }
}

// ---------------- attention kernel (M=32/warp, 2 q-tiles/CTA) ----------------
#define O_QAH 0
#define O_QAL (TB2)
#define O_QBH (2 * TB2)
#define O_QBL (3 * TB2)
#define O_KHI (4 * TB2)
#define O_KLO (5 * TB2)
#define O_VT  (6 * TB2)
#define O_MBK (7 * TB2)
#define O_MBV (7 * TB2 + 8)
#define SMEM_REQ (7 * TB2 + 16)

#define QK_HALF(HF) do {                                                        \
    _Pragma("unroll")                                                           \
    for (int mg = 0; mg < 2; ++mg)                                              \
        _Pragma("unroll")                                                       \
        for (int jn = 0; jn < 8; ++jn)                                          \
            _Pragma("unroll")                                                   \
            for (int e = 0; e < 4; ++e) sc[mg][jn][e] = 0.f;                    \
    _Pragma("unroll")                                                           \
    for (int kc = 0; kc < 8; ++kc) {                                            \
        uint32_t qoff = (uint32_t)((((kc * 2 + cA) ^ ii)) << 4);                \
        uint32_t qh0[4], qh1[4], ql0[4], ql1[4];                                \
        ldsm4(qh0, aQh + qoff); ldsm4(qh1, aQh + 4096u + qoff);                 \
        ldsm4(ql0, aQl + qoff); ldsm4(ql1, aQl + 4096u + qoff);                 \
        uint32_t koff = (uint32_t)((((kc * 2 + cB) ^ ii)) << 4);                \
        _Pragma("unroll")                                                       \
        for (int jp = 0; jp < 4; ++jp) {                                        \
            uint32_t bh[4], bl[4];                                              \
            uint32_t rowo = (uint32_t)((((HF) * 4 + jp)) * 4096);               \
            ldsm4(bh, aKh + rowo + koff);                                       \
            ldsm4(bl, aKl + rowo + koff);                                       \
            mma_bf16(sc[0][2 * jp],     qh0, bh[0], bh[1]);                     \
            mma_bf16(sc[0][2 * jp + 1], qh0, bh[2], bh[3]);                     \
            mma_bf16(sc[1][2 * jp],     qh1, bh[0], bh[1]);                     \
            mma_bf16(sc[1][2 * jp + 1], qh1, bh[2], bh[3]);                     \
            mma_bf16(sc[0][2 * jp],     qh0, bl[0], bl[1]);                     \
            mma_bf16(sc[0][2 * jp + 1], qh0, bl[2], bl[3]);                     \
            mma_bf16(sc[1][2 * jp],     qh1, bl[0], bl[1]);                     \
            mma_bf16(sc[1][2 * jp + 1], qh1, bl[2], bl[3]);                     \
            mma_bf16(sc[0][2 * jp],     ql0, bh[0], bh[1]);                     \
            mma_bf16(sc[0][2 * jp + 1], ql0, bh[2], bh[3]);                     \
            mma_bf16(sc[1][2 * jp],     ql1, bh[0], bh[1]);                     \
            mma_bf16(sc[1][2 * jp + 1], ql1, bh[2], bh[3]);                     \
        }                                                                       \
    }                                                                           \
} while (0)

#define MASK_HALF(HF) do {                                                      \
    _Pragma("unroll")                                                           \
    for (int mg = 0; mg < 2; ++mg) {                                            \
        int rl = rowbase + mg * 16 + g_, rh = rl + 8;                           \
        _Pragma("unroll")                                                       \
        for (int jn = 0; jn < 8; ++jn) {                                        \
            int col = (HF) * 64 + jn * 8 + 2 * t4;                              \
            if (col > rl) sc[mg][jn][0] = NEGBIG;                               \
            if (col + 1 > rl) sc[mg][jn][1] = NEGBIG;                           \
            if (col > rh) sc[mg][jn][2] = NEGBIG;                               \
            if (col + 1 > rh) sc[mg][jn][3] = NEGBIG;                           \
        }                                                                       \
    }                                                                           \
} while (0)

#define SOFTMAX_HALF() do {                                                     \
    float mx[4] = {-INFINITY, -INFINITY, -INFINITY, -INFINITY};                 \
    _Pragma("unroll")                                                           \
    for (int mg = 0; mg < 2; ++mg)                                              \
        _Pragma("unroll")                                                       \
        for (int jn = 0; jn < 8; ++jn) {                                        \
            mx[mg * 2]     = fmaxf(mx[mg * 2],     fmaxf(sc[mg][jn][0], sc[mg][jn][1])); \
            mx[mg * 2 + 1] = fmaxf(mx[mg * 2 + 1], fmaxf(sc[mg][jn][2], sc[mg][jn][3])); \
        }                                                                       \
    _Pragma("unroll")                                                           \
    for (int s_ = 0; s_ < 4; ++s_) {                                            \
        mx[s_] = fmaxf(mx[s_], __shfl_xor_sync(0xffffffffu, mx[s_], 1));        \
        mx[s_] = fmaxf(mx[s_], __shfl_xor_sync(0xffffffffu, mx[s_], 2));        \
    }                                                                           \
    float alv[4], sm[4] = {0.f, 0.f, 0.f, 0.f};                                 \
    _Pragma("unroll")                                                           \
    for (int s_ = 0; s_ < 4; ++s_) {                                            \
        float mn_ = fmaxf(m[s_], mx[s_]);                                       \
        alv[s_] = ex2(m[s_] - mn_);                                             \
        m[s_] = mn_;                                                            \
    }                                                                           \
    _Pragma("unroll")                                                           \
    for (int mg = 0; mg < 2; ++mg)                                              \
        _Pragma("unroll")                                                       \
        for (int jn = 0; jn < 8; ++jn) {                                        \
            pp[mg][2 * jn]     = h2ex2(f2h2(sc[mg][jn][0] - m[mg * 2],     sc[mg][jn][1] - m[mg * 2])); \
            pp[mg][2 * jn + 1] = h2ex2(f2h2(sc[mg][jn][2] - m[mg * 2 + 1], sc[mg][jn][3] - m[mg * 2 + 1])); \
            float2 fa = __half22float2(*reinterpret_cast<const __half2*>(&pp[mg][2 * jn])); \
            float2 fb = __half22float2(*reinterpret_cast<const __half2*>(&pp[mg][2 * jn + 1])); \
            sm[mg * 2] += fa.x + fa.y;                                          \
            sm[mg * 2 + 1] += fb.x + fb.y;                                      \
        }                                                                       \
    _Pragma("unroll")                                                           \
    for (int mg = 0; mg < 2; ++mg)                                              \
        _Pragma("unroll")                                                       \
        for (int jn = 0; jn < 16; ++jn) {                                       \
            oc[mg][jn][0] *= alv[mg * 2]; oc[mg][jn][1] *= alv[mg * 2];         \
            oc[mg][jn][2] *= alv[mg * 2 + 1]; oc[mg][jn][3] *= alv[mg * 2 + 1]; \
        }                                                                       \
    _Pragma("unroll")                                                           \
    for (int s_ = 0; s_ < 4; ++s_) {                                            \
        sm[s_] += __shfl_xor_sync(0xffffffffu, sm[s_], 1);                      \
        sm[s_] += __shfl_xor_sync(0xffffffffu, sm[s_], 2);                      \
        l[s_] = l[s_] * alv[s_] + sm[s_];                                       \
    }                                                                           \
} while (0)

#define PV_HALF(HF) do {                                                        \
    _Pragma("unroll")                                                           \
    for (int kcp = 0; kcp < 4; ++kcp) {                                         \
        const uint32_t* pa0 = &pp[0][4 * kcp];                                  \
        const uint32_t* pa1 = &pp[1][4 * kcp];                                  \
        uint32_t voff = (uint32_t)(((((HF) * 8 + kcp * 2 + cB) ^ ii)) << 4);    \
        _Pragma("unroll")                                                       \
        for (int jp = 0; jp < 8; ++jp) {                                        \
            uint32_t bv[4];                                                     \
            ldsm4(bv, aV + (uint32_t)(jp * 4096) + voff);                       \
            mma_f16(oc[0][2 * jp],     pa0, bv[0], bv[1]);                      \
            mma_f16(oc[0][2 * jp + 1], pa0, bv[2], bv[3]);                      \
            mma_f16(oc[1][2 * jp],     pa1, bv[0], bv[1]);                      \
            mma_f16(oc[1][2 * jp + 1], pa1, bv[2], bv[3]);                      \
        }                                                                       \
    }                                                                           \
} while (0)

__global__ __launch_bounds__(256, 1) void attn_kernel(const float* __restrict__ q,
                                                      float* __restrict__ out) {
    extern __shared__ __align__(16) uint8_t smc[];
    uint32_t sb = smem_u32(smc);

    int tid = threadIdx.x;
    int wid = tid >> 5, lane = tid & 31;
    int g_ = lane >> 2, t4 = lane & 3;
    int qq = lane >> 3, ii = lane & 7;
    int bx = blockIdx.x;
    int u = 3 - (bx & 3);            // longest-job-first
    int h = (bx >> 2) & 15, c = (bx >> 6) & 3, b = bx >> 8;

    int tile = wid >> 2;             // 0 = q-tile 2u, 1 = q-tile 2u+1
    int rowbase = (wid & 3) * 32;    // warp's 32 rows within its tile
    int myqt = 2 * u + tile;
    int jmax = 2 * u + 1;

    size_t ktb = ((size_t)((b * NH + h) * NCK + c) * 8) * TB2;

    if (tid == 0) {
        MBAR_INIT(sb + O_MBK, 1);
        MBAR_INIT(sb + O_MBV, 1);
        MBAR_EXPECT_TX(sb + O_MBK, 2 * TB2);
        bulk_g2s(sb + O_KHI, g_khi + ktb, TB2, sb + O_MBK);
        bulk_g2s(sb + O_KLO, g_klo + ktb, TB2, sb + O_MBK);
        MBAR_EXPECT_TX(sb + O_MBV, TB2);
        bulk_g2s(sb + O_VT, g_vt + ktb, TB2, sb + O_MBV);
    }

    // ---- Q: both tiles; threads 0-127 -> tile A, 128-255 -> tile B; *LOG2E
    {
        int half = tid >> 7;
        int r = tid & 127;
        int t = c * 1024 + (2 * u + half) * 128 + r;
        const float4* qr = reinterpret_cast<const float4*>(q + ((size_t)(b * T + t) * NH + h) * DH);
        const float4* cr = reinterpret_cast<const float4*>(g_cos + t * HALFD);
        const float4* sr = reinterpret_cast<const float4*>(g_sin + t * HALFD);
        uint8_t* qhi = smc + (half ? O_QBH : O_QAH);
        uint8_t* qlo = smc + (half ? O_QBL : O_QAL);
#pragma unroll
        for (int i = 0; i < 16; ++i) {
            float4 x1 = qr[i], x2 = qr[i + 16], cc = cr[i], ss = sr[i];
            float4 r1 = make_float4((x1.x * cc.x - x2.x * ss.x) * LOG2E,
                                    (x1.y * cc.y - x2.y * ss.y) * LOG2E,
                                    (x1.z * cc.z - x2.z * ss.z) * LOG2E,
                                    (x1.w * cc.w - x2.w * ss.w) * LOG2E);
            float4 r2 = make_float4((x2.x * cc.x + x1.x * ss.x) * LOG2E,
                                    (x2.y * cc.y + x1.y * ss.y) * LOG2E,
                                    (x2.z * cc.z + x1.z * ss.z) * LOG2E,
                                    (x2.w * cc.w + x1.w * ss.w) * LOG2E);
            split_store(qhi, qlo, r, 4 * i, r1);
            split_store(qhi, qlo, r, 64 + 4 * i, r2);
        }
    }
    __syncthreads();

    // lane bases
    int rA = ii + (qq & 1) * 8, cA = qq >> 1;
    int rB = ii + (qq >> 1) * 8, cB = qq & 1;
    uint32_t aQh = sb + (tile ? O_QBH : O_QAH) + (uint32_t)((rowbase + rA) * 256);
    uint32_t aQl = sb + (tile ? O_QBL : O_QAL) + (uint32_t)((rowbase + rA) * 256);
    uint32_t aKh = sb + O_KHI + (uint32_t)(rB * 256);
    uint32_t aKl = sb + O_KLO + (uint32_t)(rB * 256);
    uint32_t aV  = sb + O_VT  + (uint32_t)(rB * 256);

    float oc[2][16][4];
#pragma unroll
    for (int mg = 0; mg < 2; ++mg)
#pragma unroll
        for (int jn = 0; jn < 16; ++jn)
#pragma unroll
            for (int e = 0; e < 4; ++e) oc[mg][jn][e] = 0.f;
    float m[4] = {-INFINITY, -INFINITY, -INFINITY, -INFINITY};
    float l[4] = {0.f, 0.f, 0.f, 0.f};
    uint32_t pk = 0, pv = 0;

    for (int j = 0; j <= jmax; ++j) {
        mbar_wait(sb + O_MBK, pk);
        pk ^= 1;
        const bool act = (j <= myqt);

        float sc[2][8][4];
        uint32_t pp[2][16];

        if (act) {
            QK_HALF(0);
            if (j == myqt) MASK_HALF(0);
            SOFTMAX_HALF();
        }

        mbar_wait(sb + O_MBV, pv);
        pv ^= 1;

        if (act) {
            PV_HALF(0);
            QK_HALF(1);
        }

        // K(j) consumed by all warps (or unused): refill via warp 0
        if (j < jmax) {
            if (wid == 0) {
                BAR_SYNC(4);
                if (elect_one()) {
                    MBAR_EXPECT_TX(sb + O_MBK, 2 * TB2);
                    bulk_g2s(sb + O_KHI, g_khi + ktb + (size_t)(j + 1) * TB2, TB2, sb + O_MBK);
                    bulk_g2s(sb + O_KLO, g_klo + ktb + (size_t)(j + 1) * TB2, TB2, sb + O_MBK);
                }
            } else {
                BAR_ARRIVE(4);
            }
        }

        if (act) {
            if (j == myqt) MASK_HALF(1);
            SOFTMAX_HALF();
            PV_HALF(1);
        }

        // V(j) consumed: refill via warp 7 (always active: tile B)
        if (j < jmax) {
            if (wid == 7) {
                BAR_SYNC(5);
                if (elect_one()) {
                    MBAR_EXPECT_TX(sb + O_MBV, TB2);
                    bulk_g2s(sb + O_VT, g_vt + ktb + (size_t)(j + 1) * TB2, TB2, sb + O_MBV);
                }
            } else {
                BAR_ARRIVE(5);
            }
        }
    }

    // ---- epilogue: O / l -> gmem (32 rows per warp)
    int tq = c * 1024 + myqt * 128 + rowbase;
#pragma unroll
    for (int mg = 0; mg < 2; ++mg) {
        float i0 = 1.0f / l[mg * 2], i1 = 1.0f / l[mg * 2 + 1];
        int r0 = tq + mg * 16 + g_;
        float* o0 = out + ((size_t)(b * T + r0) * NH + h) * DV;
        float* o1 = out + ((size_t)(b * T + r0 + 8) * NH + h) * DV;
#pragma unroll
        for (int jn = 0; jn < 16; ++jn) {
            int dv = 8 * jn + 2 * t4;
            *reinterpret_cast<float2*>(o0 + dv) =
                make_float2(oc[mg][jn][0] * i0, oc[mg][jn][1] * i0);
            *reinterpret_cast<float2*>(o1 + dv) =
                make_float2(oc[mg][jn][2] * i1, oc[mg][jn][3] * i1);
        }
    }
}

// ---------------- launch -----------------------------------------------------
extern "C" void kernel_launch(void* const* d_in, const int* in_sizes, int n_in,
                              void* d_out, int out_size) {
    const float* q = (const float*)d_in[0];
    const float* k = (const float*)d_in[1];
    const float* v = (const float*)d_in[2];
    const int* start = (const int*)d_in[3];
    float* out = (float*)d_out;

    cudaFuncSetAttribute(attn_kernel, cudaFuncAttributeMaxDynamicSharedMemorySize, SMEM_REQ);
    cudaFuncSetAttribute(kprep_kernel, cudaFuncAttributeMaxDynamicSharedMemorySize, 2 * TB2);

    tables_kernel<<<(T * HALFD + 255) / 256, 256>>>(start);
    kprep_kernel<<<NTILES, 256, 2 * TB2>>>(k);
    vprep_kernel<<<NTILES, 256>>>(v);
    attn_kernel<<<NB * NH * NCK * 4, 256, SMEM_REQ>>>(q, out);
}

// round 13
// speedup vs baseline: 1.2718x; 1.2718x over previous
#include <cuda_runtime.h>
#include <cuda_bf16.h>
#include <cuda_fp16.h>
#include <cstdint>
#include <math.h>

#define NB 4
#define T 4096
#define NH 16
#define DH 128
#define DV 128
#define CHUNK 1024
#define NCK 4
#define HALFD 64
#define LOG2E 1.4426950408889634f
#define NEGBIG -1e30f

#define ROWSTRIDE 272                 // 128*2B + 16B pad -> conflict-free ldmatrix
#define TILE_BYTES (128 * ROWSTRIDE)  // 34816
#define NTILES (NB * NH * NCK * 8)    // 2048

// ---------------- device scratch (no cudaMalloc allowed) -------------------
__device__ __align__(128) uint8_t g_khi[(size_t)NTILES * TILE_BYTES];
__device__ __align__(128) uint8_t g_klo[(size_t)NTILES * TILE_BYTES];
__device__ __align__(128) uint8_t g_vt [(size_t)NTILES * TILE_BYTES];
__device__ float   g_cos[T * HALFD];
__device__ float   g_sin[T * HALFD];

// ---------------- helpers ---------------------------------------------------
__device__ __forceinline__ uint32_t smem_u32(const void* p) {
    uint32_t a;
    asm("{ .reg .u64 t; cvta.to.shared.u64 t, %1; cvt.u32.u64 %0, t; }"
        : "=r"(a) : "l"(p));
    return a;
}

__device__ __forceinline__ uint32_t elect_one() {
    uint32_t p;
    asm volatile("{ .reg .pred p; elect.sync _|p, 0xFFFFFFFF; selp.b32 %0, 1, 0, p; }"
                 : "=r"(p));
    return p;
}

__device__ __forceinline__ float ex2(float x) {
    float y;
    asm("ex2.approx.ftz.f32 %0, %1;" : "=f"(y) : "f"(x));
    return y;
}

__device__ __forceinline__ uint32_t h2ex2(uint32_t x) {
    uint32_t y;
    asm("ex2.approx.f16x2 %0, %1;" : "=r"(y) : "r"(x));
    return y;
}

__device__ __forceinline__ uint32_t f2h2(float a, float b) {
    uint32_t y;
    asm("cvt.rn.f16x2.f32 %0, %2, %1;" : "=r"(y) : "f"(a), "f"(b));
    return y;
}

__device__ __forceinline__ uint32_t bf2u(__nv_bfloat16 a, __nv_bfloat16 b) {
    __nv_bfloat162 t = __halves2bfloat162(a, b);
    return *reinterpret_cast<uint32_t*>(&t);
}

// row-major tile, 272B row stride
__device__ __forceinline__ uint32_t tile_off(int r, int c) {
    return (uint32_t)(r * ROWSTRIDE + c * 2);
}

__device__ __forceinline__ void split_store(uint8_t* hi, uint8_t* lo, int r, int kd, float4 v) {
    __nv_bfloat16 h0 = __float2bfloat16_rn(v.x);
    __nv_bfloat16 h1 = __float2bfloat16_rn(v.y);
    __nv_bfloat16 h2 = __float2bfloat16_rn(v.z);
    __nv_bfloat16 h3 = __float2bfloat16_rn(v.w);
    __nv_bfloat16 l0 = __float2bfloat16_rn(v.x - __bfloat162float(h0));
    __nv_bfloat16 l1 = __float2bfloat16_rn(v.y - __bfloat162float(h1));
    __nv_bfloat16 l2 = __float2bfloat16_rn(v.z - __bfloat162float(h2));
    __nv_bfloat16 l3 = __float2bfloat16_rn(v.w - __bfloat162float(h3));
    uint32_t off = tile_off(r, kd);
    *reinterpret_cast<uint2*>(hi + off) = make_uint2(bf2u(h0, h1), bf2u(h2, h3));
    *reinterpret_cast<uint2*>(lo + off) = make_uint2(bf2u(l0, l1), bf2u(l2, l3));
}

// ---------------- mbarrier / bulk copy (sm_90 baseline) ---------------------
#define MBAR_INIT(mb, n) \
    asm volatile("mbarrier.init.shared.b64 [%0], %1;" :: "r"(mb), "r"((uint32_t)(n)) : "memory")
#define MBAR_EXPECT_TX(mb, bytes) \
    asm volatile("mbarrier.arrive.expect_tx.shared.b64 _, [%0], %1;" \
                 :: "r"(mb), "r"((uint32_t)(bytes)) : "memory")

__device__ __forceinline__ void mbar_wait(uint32_t mb, uint32_t phase) {
    asm volatile(
        "{\n\t.reg .pred P;\n\t"
        "LAB_W%=:\n\t"
        "mbarrier.try_wait.parity.acquire.cta.shared::cta.b64 P, [%0], %1, 0x989680;\n\t"
        "@P bra.uni LAB_D%=;\n\t"
        "bra.uni LAB_W%=;\n\t"
        "LAB_D%=:\n\t}"
        :: "r"(mb), "r"(phase) : "memory");
}

__device__ __forceinline__ void bulk_g2s(uint32_t dst, const void* src, uint32_t bytes, uint32_t mb) {
    asm volatile(
        "cp.async.bulk.shared::cluster.global.mbarrier::complete_tx::bytes [%0], [%1], %2, [%3];"
        :: "r"(dst), "l"(src), "r"(bytes), "r"(mb) : "memory");
}

#define BAR_ARRIVE(id) asm volatile("bar.arrive %0, 256;" :: "r"(id) : "memory")
#define BAR_SYNC(id)   asm volatile("bar.sync %0, 256;" :: "r"(id) : "memory")

// ---------------- mma.sync + ldmatrix ---------------------------------------
__device__ __forceinline__ void ldsm4(uint32_t* r, uint32_t addr) {
    asm volatile("ldmatrix.sync.aligned.m8n8.x4.shared.b16 {%0,%1,%2,%3}, [%4];"
                 : "=r"(r[0]), "=r"(r[1]), "=r"(r[2]), "=r"(r[3]) : "r"(addr));
}

__device__ __forceinline__ void mma_bf16(float* c, const uint32_t* a, uint32_t b0, uint32_t b1) {
    asm volatile(
        "mma.sync.aligned.m16n8k16.row.col.f32.bf16.bf16.f32 "
        "{%0,%1,%2,%3}, {%4,%5,%6,%7}, {%8,%9}, {%0,%1,%2,%3};"
        : "+f"(c[0]), "+f"(c[1]), "+f"(c[2]), "+f"(c[3])
        : "r"(a[0]), "r"(a[1]), "r"(a[2]), "r"(a[3]), "r"(b0), "r"(b1));
}

__device__ __forceinline__ void mma_f16(float* c, const uint32_t* a, uint32_t b0, uint32_t b1) {
    asm volatile(
        "mma.sync.aligned.m16n8k16.row.col.f32.f16.f16.f32 "
        "{%0,%1,%2,%3}, {%4,%5,%6,%7}, {%8,%9}, {%0,%1,%2,%3};"
        : "+f"(c[0]), "+f"(c[1]), "+f"(c[2]), "+f"(c[3])
        : "r"(a[0]), "r"(a[1]), "r"(a[2]), "r"(a[3]), "r"(b0), "r"(b1));
}

// ---------------- prep kernels ----------------------------------------------
__global__ void tables_kernel(const int* __restrict__ startp) {
    __shared__ float invf_s[HALFD];
    int tid = threadIdx.x;
    if (tid < HALFD) {
        double invf = exp(-(double)tid * (log(10000.0) / (double)HALFD));
        invf_s[tid] = (float)invf;
    }
    __syncthreads();
    int idx = blockIdx.x * blockDim.x + tid;
    if (idx >= T * HALFD) return;
    int t = idx >> 6, i = idx & 63;
    float ang = (float)(*startp + t) * invf_s[i];
    float s, c;
    sincosf(ang, &s, &c);
    g_cos[idx] = c;
    g_sin[idx] = s;
}

// fused prep: blocks [0,NTILES) build K hi/lo tiles (no smem, 16B stores);
// blocks [NTILES, 2*NTILES) build V^T tiles (smem transpose). Independent
// halves run concurrently in one launch.
__global__ __launch_bounds__(256) void kvprep_kernel(const float* __restrict__ k,
                                                     const float* __restrict__ v) {
    __shared__ __half st[128 * 130];
    int bix = blockIdx.x;
    int tid = threadIdx.x;

    if (bix < NTILES) {
        int tix = bix;
        int j = tix & 7, c = (tix >> 3) & 3, h = (tix >> 5) & 15, b = tix >> 9;
        size_t tb = (size_t)tix * TILE_BYTES;
        uint8_t* hi = g_khi + tb;
        uint8_t* lo = g_klo + tb;
#pragma unroll
        for (int p = 0; p < 8; ++p) {
            int u = tid + p * 256;        // (row, 8-col group)
            int r = u >> 4, grp = u & 15;
            int t = c * 1024 + j * 128 + r;
            const float* kr = k + ((size_t)(b * T + t) * NH + h) * DH;
            int c0 = grp * 8;
            float o[8];
            if (grp < 8) {
                const float4* x1 = reinterpret_cast<const float4*>(kr + c0);
                const float4* x2 = reinterpret_cast<const float4*>(kr + c0 + 64);
                const float4* cc = reinterpret_cast<const float4*>(g_cos + t * HALFD + c0);
                const float4* ss = reinterpret_cast<const float4*>(g_sin + t * HALFD + c0);
#pragma unroll
                for (int q2 = 0; q2 < 2; ++q2) {
                    float4 a = x1[q2], bb = x2[q2], cv = cc[q2], sv = ss[q2];
                    o[4 * q2 + 0] = a.x * cv.x - bb.x * sv.x;
                    o[4 * q2 + 1] = a.y * cv.y - bb.y * sv.y;
                    o[4 * q2 + 2] = a.z * cv.z - bb.z * sv.z;
                    o[4 * q2 + 3] = a.w * cv.w - bb.w * sv.w;
                }
            } else {
                int cd = c0 - 64;
                const float4* x1 = reinterpret_cast<const float4*>(kr + cd);
                const float4* x2 = reinterpret_cast<const float4*>(kr + c0);
                const float4* cc = reinterpret_cast<const float4*>(g_cos + t * HALFD + cd);
                const float4* ss = reinterpret_cast<const float4*>(g_sin + t * HALFD + cd);
#pragma unroll
                for (int q2 = 0; q2 < 2; ++q2) {
                    float4 a = x1[q2], bb = x2[q2], cv = cc[q2], sv = ss[q2];
                    o[4 * q2 + 0] = bb.x * cv.x + a.x * sv.x;
                    o[4 * q2 + 1] = bb.y * cv.y + a.y * sv.y;
                    o[4 * q2 + 2] = bb.z * cv.z + a.z * sv.z;
                    o[4 * q2 + 3] = bb.w * cv.w + a.w * sv.w;
                }
            }
            uint32_t hw[4], lw[4];
#pragma unroll
            for (int e = 0; e < 4; ++e) {
                __nv_bfloat16 h0 = __float2bfloat16_rn(o[2 * e]);
                __nv_bfloat16 h1 = __float2bfloat16_rn(o[2 * e + 1]);
                __nv_bfloat16 l0 = __float2bfloat16_rn(o[2 * e] - __bfloat162float(h0));
                __nv_bfloat16 l1 = __float2bfloat16_rn(o[2 * e + 1] - __bfloat162float(h1));
                hw[e] = bf2u(h0, h1);
                lw[e] = bf2u(l0, l1);
            }
            uint32_t off = tile_off(r, c0);
            *reinterpret_cast<uint4*>(hi + off) = make_uint4(hw[0], hw[1], hw[2], hw[3]);
            *reinterpret_cast<uint4*>(lo + off) = make_uint4(lw[0], lw[1], lw[2], lw[3]);
        }
    } else {
        int tix = bix - NTILES;
        int j = tix & 7, c = (tix >> 3) & 3, h = (tix >> 5) & 15, b = tix >> 9;
        int t0 = c * 1024 + j * 128;
        for (int e = tid; e < 16384; e += 256) {
            int kl = e >> 7, dv = e & 127;
            float val = v[((size_t)(b * T + t0 + kl) * NH + h) * DV + dv];
            st[dv * 130 + kl] = __float2half_rn(val);
        }
        __syncthreads();
        uint8_t* dst = g_vt + (size_t)tix * TILE_BYTES;
        for (int e = tid; e < 2048; e += 256) {
            int dv = e >> 4, ch = e & 15;
            const uint32_t* s = reinterpret_cast<const uint32_t*>(&st[dv * 130 + ch * 8]);
            uint4 w = make_uint4(s[0], s[1], s[2], s[3]);
            *reinterpret_cast<uint4*>(dst + (uint32_t)dv * ROWSTRIDE + ch * 16) = w;
        }
    }
}

// ---------------- attention kernel ------------------------------------------
#define O_QHI 0
#define O_QLO (TILE_BYTES)
#define O_KHI (2 * TILE_BYTES)
#define O_KLO (3 * TILE_BYTES)
#define O_VT  (4 * TILE_BYTES)
#define O_MBK (5 * TILE_BYTES)
#define O_MBV (5 * TILE_BYTES + 8)
#define SMEM_REQ (5 * TILE_BYTES + 16)

__global__ __launch_bounds__(256, 1) void attn_kernel(const float* __restrict__ q,
                                                      float* __restrict__ out) {
    extern __shared__ __align__(16) uint8_t smc[];
    uint32_t sb = smem_u32(smc);

    int tid = threadIdx.x;
    int wid = tid >> 5, lane = tid & 31;
    int g = lane >> 2, t4 = lane & 3;
    int qq = lane >> 3, ii = lane & 7;
    int bx = blockIdx.x;
    int qt = 7 - (bx & 7);   // longest-job-first within scheduling order
    int h = (bx >> 3) & 15, c = (bx >> 7) & 3, b = bx >> 9;

    size_t ktb = ((size_t)((b * NH + h) * NCK + c) * 8) * TILE_BYTES;

    if (tid == 0) {
        MBAR_INIT(sb + O_MBK, 1);
        MBAR_INIT(sb + O_MBV, 1);
        // prologue (same thread: ordered after init)
        MBAR_EXPECT_TX(sb + O_MBK, 2 * TILE_BYTES);
        bulk_g2s(sb + O_KHI, g_khi + ktb, TILE_BYTES, sb + O_MBK);
        bulk_g2s(sb + O_KLO, g_klo + ktb, TILE_BYTES, sb + O_MBK);
        MBAR_EXPECT_TX(sb + O_MBV, TILE_BYTES);
        bulk_g2s(sb + O_VT, g_vt + ktb, TILE_BYTES, sb + O_MBV);
    }

    // ---- Q: load + RoPE, PRE-SCALED by log2(e), bf16 hi/lo split into SMEM
    if (tid < 128) {
        int r = tid;
        int t = c * 1024 + qt * 128 + r;
        const float4* qr = reinterpret_cast<const float4*>(q + ((size_t)(b * T + t) * NH + h) * DH);
        const float4* cr = reinterpret_cast<const float4*>(g_cos + t * HALFD);
        const float4* sr = reinterpret_cast<const float4*>(g_sin + t * HALFD);
        uint8_t* qhi = smc + O_QHI;
        uint8_t* qlo = smc + O_QLO;
#pragma unroll
        for (int i = 0; i < 16; ++i) {
            float4 x1 = qr[i], x2 = qr[i + 16], cc = cr[i], ss = sr[i];
            float4 r1 = make_float4((x1.x * cc.x - x2.x * ss.x) * LOG2E,
                                    (x1.y * cc.y - x2.y * ss.y) * LOG2E,
                                    (x1.z * cc.z - x2.z * ss.z) * LOG2E,
                                    (x1.w * cc.w - x2.w * ss.w) * LOG2E);
            float4 r2 = make_float4((x2.x * cc.x + x1.x * ss.x) * LOG2E,
                                    (x2.y * cc.y + x1.y * ss.y) * LOG2E,
                                    (x2.z * cc.z + x1.z * ss.z) * LOG2E,
                                    (x2.w * cc.w + x1.w * ss.w) * LOG2E);
            split_store(qhi, qlo, r, 4 * i, r1);
            split_store(qhi, qlo, r, 64 + 4 * i, r2);
        }
    }
    __syncthreads();   // Q ready for all warps

    // ldmatrix lane offsets
    uint32_t offA = (uint32_t)((ii + (qq & 1) * 8) * ROWSTRIDE + ((qq >> 1) * 8) * 2);
    uint32_t offB = (uint32_t)((ii + (qq >> 1) * 8) * ROWSTRIDE + ((qq & 1) * 8) * 2);
    uint32_t aQhi = sb + O_QHI + (uint32_t)(wid * 16 * ROWSTRIDE) + offA;
    uint32_t aQlo = sb + O_QLO + (uint32_t)(wid * 16 * ROWSTRIDE) + offA;
    uint32_t aKhi = sb + O_KHI + offB;
    uint32_t aKlo = sb + O_KLO + offB;
    uint32_t aVt  = sb + O_VT  + offB;

    float oc[16][4];
#pragma unroll
    for (int jn = 0; jn < 16; ++jn)
#pragma unroll
        for (int e = 0; e < 4; ++e) oc[jn][e] = 0.f;
    float m0 = -INFINITY, m1 = -INFINITY, l0 = 0.f, l1 = 0.f;
    uint32_t pk = 0, pv = 0;

    for (int j = 0; j <= qt; ++j) {
        mbar_wait(sb + O_MBK, pk);
        pk ^= 1;

        // ---- S' = (Q*log2e)*K : scores in log2 units
        float sc[16][4];
#pragma unroll
        for (int jn = 0; jn < 16; ++jn)
#pragma unroll
            for (int e = 0; e < 4; ++e) sc[jn][e] = 0.f;

#pragma unroll
        for (int kc = 0; kc < 8; ++kc) {
            uint32_t qh[4], qlr[4];
            ldsm4(qh, aQhi + kc * 32);
            ldsm4(qlr, aQlo + kc * 32);
#pragma unroll
            for (int jp = 0; jp < 8; ++jp) {
                uint32_t bh[4], bl[4];
                ldsm4(bh, aKhi + (uint32_t)(jp * 16 * ROWSTRIDE) + kc * 32);
                ldsm4(bl, aKlo + (uint32_t)(jp * 16 * ROWSTRIDE) + kc * 32);
                mma_bf16(sc[2 * jp],     qh,  bh[0], bh[1]);
                mma_bf16(sc[2 * jp + 1], qh,  bh[2], bh[3]);
                mma_bf16(sc[2 * jp],     qh,  bl[0], bl[1]);
                mma_bf16(sc[2 * jp + 1], qh,  bl[2], bl[3]);
                mma_bf16(sc[2 * jp],     qlr, bh[0], bh[1]);
                mma_bf16(sc[2 * jp + 1], qlr, bh[2], bh[3]);
            }
        }

        // K(j) consumed: 7 warps fire-and-forget; warp 0 waits + refills K
        if (j < qt) {
            if (wid == 0) {
                BAR_SYNC(4);
                if (elect_one()) {
                    MBAR_EXPECT_TX(sb + O_MBK, 2 * TILE_BYTES);
                    bulk_g2s(sb + O_KHI, g_khi + ktb + (size_t)(j + 1) * TILE_BYTES, TILE_BYTES, sb + O_MBK);
                    bulk_g2s(sb + O_KLO, g_klo + ktb + (size_t)(j + 1) * TILE_BYTES, TILE_BYTES, sb + O_MBK);
                }
            } else {
                BAR_ARRIVE(4);
            }
        }

        // ---- causal mask on diagonal tile
        if (j == qt) {
            int row0 = wid * 16 + g, row1 = row0 + 8;
#pragma unroll
            for (int jn = 0; jn < 16; ++jn) {
                int col = 8 * jn + 2 * t4;
                if (col > row0) sc[jn][0] = NEGBIG;
                if (col + 1 > row0) sc[jn][1] = NEGBIG;
                if (col > row1) sc[jn][2] = NEGBIG;
                if (col + 1 > row1) sc[jn][3] = NEGBIG;
            }
        }

        // ---- row max (4 parallel chains) + alpha
        float mx0a = -INFINITY, mx0b = -INFINITY, mx1a = -INFINITY, mx1b = -INFINITY;
#pragma unroll
        for (int jn = 0; jn < 16; jn += 2) {
            mx0a = fmaxf(mx0a, fmaxf(sc[jn][0], sc[jn][1]));
            mx1a = fmaxf(mx1a, fmaxf(sc[jn][2], sc[jn][3]));
            mx0b = fmaxf(mx0b, fmaxf(sc[jn + 1][0], sc[jn + 1][1]));
            mx1b = fmaxf(mx1b, fmaxf(sc[jn + 1][2], sc[jn + 1][3]));
        }
        float mx0 = fmaxf(mx0a, mx0b), mx1 = fmaxf(mx1a, mx1b);
        mx0 = fmaxf(mx0, __shfl_xor_sync(0xffffffffu, mx0, 1));
        mx0 = fmaxf(mx0, __shfl_xor_sync(0xffffffffu, mx0, 2));
        mx1 = fmaxf(mx1, __shfl_xor_sync(0xffffffffu, mx1, 1));
        mx1 = fmaxf(mx1, __shfl_xor_sync(0xffffffffu, mx1, 2));
        float mn0 = fmaxf(m0, mx0), mn1 = fmaxf(m1, mx1);
        float al0 = ex2(m0 - mn0), al1 = ex2(m1 - mn1);
        m0 = mn0; m1 = mn1;
        l0 *= al0; l1 *= al1;

        // ---- P = 2^(s'-m') via paired f16 ex2 (direct fp16 MMA fragments)
        uint32_t pp[32];
#pragma unroll
        for (int jn = 0; jn < 16; ++jn) {
            pp[2 * jn]     = h2ex2(f2h2(sc[jn][0] - mn0, sc[jn][1] - mn0));
            pp[2 * jn + 1] = h2ex2(f2h2(sc[jn][2] - mn1, sc[jn][3] - mn1));
            oc[jn][0] *= al0; oc[jn][1] *= al0;
            oc[jn][2] *= al1; oc[jn][3] *= al1;
        }

        mbar_wait(sb + O_MBV, pv);
        pv ^= 1;

        // ---- O += P16 * V^T ; l summed from the same f16 P values
        float s0 = 0.f, s1 = 0.f;
#pragma unroll
        for (int kc = 0; kc < 8; ++kc) {
            const uint32_t* pa = pp + 4 * kc;
            {
                float2 f0 = __half22float2(*reinterpret_cast<const __half2*>(pa + 0));
                float2 f1 = __half22float2(*reinterpret_cast<const __half2*>(pa + 1));
                float2 f2 = __half22float2(*reinterpret_cast<const __half2*>(pa + 2));
                float2 f3 = __half22float2(*reinterpret_cast<const __half2*>(pa + 3));
                s0 += f0.x + f0.y + f2.x + f2.y;
                s1 += f1.x + f1.y + f3.x + f3.y;
            }
#pragma unroll
            for (int jp = 0; jp < 8; ++jp) {
                uint32_t bv[4];
                ldsm4(bv, aVt + (uint32_t)(jp * 16 * ROWSTRIDE) + kc * 32);
                mma_f16(oc[2 * jp], pa, bv[0], bv[1]);
                mma_f16(oc[2 * jp + 1], pa, bv[2], bv[3]);
            }
        }
        s0 += __shfl_xor_sync(0xffffffffu, s0, 1);
        s0 += __shfl_xor_sync(0xffffffffu, s0, 2);
        s1 += __shfl_xor_sync(0xffffffffu, s1, 1);
        s1 += __shfl_xor_sync(0xffffffffu, s1, 2);
        l0 += s0; l1 += s1;

        // V(j) consumed: 7 warps fire-and-forget; warp 7 waits + refills V
        if (j < qt) {
            if (wid == 7) {
                BAR_SYNC(5);
                if (elect_one()) {
                    MBAR_EXPECT_TX(sb + O_MBV, TILE_BYTES);
                    bulk_g2s(sb + O_VT, g_vt + ktb + (size_t)(j + 1) * TILE_BYTES, TILE_BYTES, sb + O_MBV);
                }
            } else {
                BAR_ARRIVE(5);
            }
        }
    }

    // ---- epilogue: O / l -> gmem
    float inv0 = 1.0f / l0, inv1 = 1.0f / l1;
    int t0g = c * 1024 + qt * 128 + wid * 16 + g;
    float* o0 = out + ((size_t)(b * T + t0g) * NH + h) * DV;
    float* o1 = out + ((size_t)(b * T + t0g + 8) * NH + h) * DV;
#pragma unroll
    for (int jn = 0; jn < 16; ++jn) {
        int dv = 8 * jn + 2 * t4;
        *reinterpret_cast<float2*>(o0 + dv) = make_float2(oc[jn][0] * inv0, oc[jn][1] * inv0);
        *reinterpret_cast<float2*>(o1 + dv) = make_float2(oc[jn][2] * inv1, oc[jn][3] * inv1);
    }
}

// ---------------- launch -----------------------------------------------------
extern "C" void kernel_launch(void* const* d_in, const int* in_sizes, int n_in,
                              void* d_out, int out_size) {
    const float* q = (const float*)d_in[0];
    const float* k = (const float*)d_in[1];
    const float* v = (const float*)d_in[2];
    const int* start = (const int*)d_in[3];
    float* out = (float*)d_out;

    cudaFuncSetAttribute(attn_kernel, cudaFuncAttributeMaxDynamicSharedMemorySize, SMEM_REQ);

    tables_kernel<<<(T * HALFD + 255) / 256, 256>>>(start);
    kvprep_kernel<<<2 * NTILES, 256>>>(k, v);
    attn_kernel<<<NB * NH * NCK * 8, 256, SMEM_REQ>>>(q, out);
}

// round 14
// speedup vs baseline: 1.3648x; 1.0731x over previous
#include <cuda_runtime.h>
#include <cuda_bf16.h>
#include <cuda_fp16.h>
#include <cstdint>
#include <math.h>

#define NB 4
#define T 4096
#define NH 16
#define DH 128
#define DV 128
#define CHUNK 1024
#define NCK 4
#define HALFD 64
#define LOG2E 1.4426950408889634f
#define NEGBIG -1e30f

#define ROWSTRIDE 272                 // 128*2B + 16B pad -> conflict-free ldmatrix
#define TILE_BYTES (128 * ROWSTRIDE)  // 34816
#define NTILES (NB * NH * NCK * 8)    // 2048

// ---------------- device scratch (no cudaMalloc allowed) -------------------
__device__ __align__(128) uint8_t g_khi[(size_t)NTILES * TILE_BYTES];
__device__ __align__(128) uint8_t g_klo[(size_t)NTILES * TILE_BYTES];
__device__ __align__(128) uint8_t g_vt [(size_t)NTILES * TILE_BYTES];
__device__ float   g_cos[T * HALFD];
__device__ float   g_sin[T * HALFD];

// ---------------- helpers ---------------------------------------------------
__device__ __forceinline__ uint32_t smem_u32(const void* p) {
    uint32_t a;
    asm("{ .reg .u64 t; cvta.to.shared.u64 t, %1; cvt.u32.u64 %0, t; }"
        : "=r"(a) : "l"(p));
    return a;
}

__device__ __forceinline__ uint32_t elect_one() {
    uint32_t p;
    asm volatile("{ .reg .pred p; elect.sync _|p, 0xFFFFFFFF; selp.b32 %0, 1, 0, p; }"
                 : "=r"(p));
    return p;
}

__device__ __forceinline__ float ex2(float x) {
    float y;
    asm("ex2.approx.ftz.f32 %0, %1;" : "=f"(y) : "f"(x));
    return y;
}

__device__ __forceinline__ uint32_t h2ex2(uint32_t x) {
    uint32_t y;
    asm("ex2.approx.f16x2 %0, %1;" : "=r"(y) : "r"(x));
    return y;
}

__device__ __forceinline__ uint32_t f2h2(float a, float b) {
    uint32_t y;
    asm("cvt.rn.f16x2.f32 %0, %2, %1;" : "=r"(y) : "f"(a), "f"(b));
    return y;
}

__device__ __forceinline__ uint32_t bf2u(__nv_bfloat16 a, __nv_bfloat16 b) {
    __nv_bfloat162 t = __halves2bfloat162(a, b);
    return *reinterpret_cast<uint32_t*>(&t);
}

// row-major tile, 272B row stride
__device__ __forceinline__ uint32_t tile_off(int r, int c) {
    return (uint32_t)(r * ROWSTRIDE + c * 2);
}

__device__ __forceinline__ void split_store(uint8_t* hi, uint8_t* lo, int r, int kd, float4 v) {
    __nv_bfloat16 h0 = __float2bfloat16_rn(v.x);
    __nv_bfloat16 h1 = __float2bfloat16_rn(v.y);
    __nv_bfloat16 h2 = __float2bfloat16_rn(v.z);
    __nv_bfloat16 h3 = __float2bfloat16_rn(v.w);
    __nv_bfloat16 l0 = __float2bfloat16_rn(v.x - __bfloat162float(h0));
    __nv_bfloat16 l1 = __float2bfloat16_rn(v.y - __bfloat162float(h1));
    __nv_bfloat16 l2 = __float2bfloat16_rn(v.z - __bfloat162float(h2));
    __nv_bfloat16 l3 = __float2bfloat16_rn(v.w - __bfloat162float(h3));
    uint32_t off = tile_off(r, kd);
    *reinterpret_cast<uint2*>(hi + off) = make_uint2(bf2u(h0, h1), bf2u(h2, h3));
    *reinterpret_cast<uint2*>(lo + off) = make_uint2(bf2u(l0, l1), bf2u(l2, l3));
}

// ---------------- mbarrier / bulk copy (sm_90 baseline) ---------------------
#define MBAR_INIT(mb, n) \
    asm volatile("mbarrier.init.shared.b64 [%0], %1;" :: "r"(mb), "r"((uint32_t)(n)) : "memory")
#define MBAR_EXPECT_TX(mb, bytes) \
    asm volatile("mbarrier.arrive.expect_tx.shared.b64 _, [%0], %1;" \
                 :: "r"(mb), "r"((uint32_t)(bytes)) : "memory")

__device__ __forceinline__ void mbar_wait(uint32_t mb, uint32_t phase) {
    asm volatile(
        "{\n\t.reg .pred P;\n\t"
        "LAB_W%=:\n\t"
        "mbarrier.try_wait.parity.acquire.cta.shared::cta.b64 P, [%0], %1, 0x989680;\n\t"
        "@P bra.uni LAB_D%=;\n\t"
        "bra.uni LAB_W%=;\n\t"
        "LAB_D%=:\n\t}"
        :: "r"(mb), "r"(phase) : "memory");
}

__device__ __forceinline__ void bulk_g2s(uint32_t dst, const void* src, uint32_t bytes, uint32_t mb) {
    asm volatile(
        "cp.async.bulk.shared::cluster.global.mbarrier::complete_tx::bytes [%0], [%1], %2, [%3];"
        :: "r"(dst), "l"(src), "r"(bytes), "r"(mb) : "memory");
}

#define BAR_ARRIVE(id) asm volatile("bar.arrive %0, 256;" :: "r"(id) : "memory")
#define BAR_SYNC(id)   asm volatile("bar.sync %0, 256;" :: "r"(id) : "memory")

// ---------------- mma.sync + ldmatrix ---------------------------------------
__device__ __forceinline__ void ldsm4(uint32_t* r, uint32_t addr) {
    asm volatile("ldmatrix.sync.aligned.m8n8.x4.shared.b16 {%0,%1,%2,%3}, [%4];"
                 : "=r"(r[0]), "=r"(r[1]), "=r"(r[2]), "=r"(r[3]) : "r"(addr));
}

__device__ __forceinline__ void mma_bf16(float* c, const uint32_t* a, uint32_t b0, uint32_t b1) {
    asm volatile(
        "mma.sync.aligned.m16n8k16.row.col.f32.bf16.bf16.f32 "
        "{%0,%1,%2,%3}, {%4,%5,%6,%7}, {%8,%9}, {%0,%1,%2,%3};"
        : "+f"(c[0]), "+f"(c[1]), "+f"(c[2]), "+f"(c[3])
        : "r"(a[0]), "r"(a[1]), "r"(a[2]), "r"(a[3]), "r"(b0), "r"(b1));
}

__device__ __forceinline__ void mma_f16(float* c, const uint32_t* a, uint32_t b0, uint32_t b1) {
    asm volatile(
        "mma.sync.aligned.m16n8k16.row.col.f32.f16.f16.f32 "
        "{%0,%1,%2,%3}, {%4,%5,%6,%7}, {%8,%9}, {%0,%1,%2,%3};"
        : "+f"(c[0]), "+f"(c[1]), "+f"(c[2]), "+f"(c[3])
        : "r"(a[0]), "r"(a[1]), "r"(a[2]), "r"(a[3]), "r"(b0), "r"(b1));
}

// ---------------- prep kernels ----------------------------------------------
__global__ void tables_kernel(const int* __restrict__ startp) {
    __shared__ float invf_s[HALFD];
    int tid = threadIdx.x;
    if (tid < HALFD) {
        double invf = exp(-(double)tid * (log(10000.0) / (double)HALFD));
        invf_s[tid] = (float)invf;
    }
    __syncthreads();
    int idx = blockIdx.x * blockDim.x + tid;
    if (idx >= T * HALFD) return;
    int t = idx >> 6, i = idx & 63;
    float ang = (float)(*startp + t) * invf_s[i];
    float s, c;
    sincosf(ang, &s, &c);
    g_cos[idx] = c;
    g_sin[idx] = s;
}

// single-pass kprep: read K once, RoPE + split, store 8B runs directly to the
// gmem tile image (16 threads/row -> two contiguous 128B store runs per row).
__global__ __launch_bounds__(256) void kprep_kernel(const float* __restrict__ k) {
    int tix = blockIdx.x;
    int j = tix & 7, c = (tix >> 3) & 3, h = (tix >> 5) & 15, b = tix >> 9;
    int tid = threadIdx.x;
    size_t tb = (size_t)tix * TILE_BYTES;
    uint8_t* hi = g_khi + tb;
    uint8_t* lo = g_klo + tb;

#pragma unroll
    for (int p = 0; p < 8; ++p) {
        int u = tid + p * 256;            // 2048 units: (row, float4-col of first half)
        int r = u >> 4, i = u & 15;
        int t = c * 1024 + j * 128 + r;
        const float* kr = k + ((size_t)(b * T + t) * NH + h) * DH;
        float4 x1 = *reinterpret_cast<const float4*>(kr + 4 * i);
        float4 x2 = *reinterpret_cast<const float4*>(kr + 64 + 4 * i);
        float4 cc = *reinterpret_cast<const float4*>(g_cos + t * HALFD + 4 * i);
        float4 ss = *reinterpret_cast<const float4*>(g_sin + t * HALFD + 4 * i);
        float4 r1 = make_float4(x1.x * cc.x - x2.x * ss.x, x1.y * cc.y - x2.y * ss.y,
                                x1.z * cc.z - x2.z * ss.z, x1.w * cc.w - x2.w * ss.w);
        float4 r2 = make_float4(x2.x * cc.x + x1.x * ss.x, x2.y * cc.y + x1.y * ss.y,
                                x2.z * cc.z + x1.z * ss.z, x2.w * cc.w + x1.w * ss.w);
        split_store(hi, lo, r, 4 * i, r1);
        split_store(hi, lo, r, 64 + 4 * i, r2);
    }
}

// V -> V^T tiles [dv][kpos] as f16, row stride 272
__global__ __launch_bounds__(256) void vprep_kernel(const float* __restrict__ v) {
    __shared__ __half st[128 * 130];
    int tix = blockIdx.x;
    int j = tix & 7, c = (tix >> 3) & 3, h = (tix >> 5) & 15, b = tix >> 9;
    int t0 = c * 1024 + j * 128;
    for (int e = threadIdx.x; e < 16384; e += 256) {
        int kl = e >> 7, dv = e & 127;
        float val = v[((size_t)(b * T + t0 + kl) * NH + h) * DV + dv];
        st[dv * 130 + kl] = __float2half_rn(val);
    }
    __syncthreads();
    uint8_t* dst = g_vt + (size_t)tix * TILE_BYTES;
    for (int e = threadIdx.x; e < 2048; e += 256) {
        int dv = e >> 4, ch = e & 15;
        const uint32_t* s = reinterpret_cast<const uint32_t*>(&st[dv * 130 + ch * 8]);
        uint4 w = make_uint4(s[0], s[1], s[2], s[3]);
        *reinterpret_cast<uint4*>(dst + (uint32_t)dv * ROWSTRIDE + ch * 16) = w;
    }
}

// ---------------- attention kernel ------------------------------------------
#define O_QHI 0
#define O_QLO (TILE_BYTES)
#define O_KHI (2 * TILE_BYTES)
#define O_KLO (3 * TILE_BYTES)
#define O_VT  (4 * TILE_BYTES)
#define O_MBK (5 * TILE_BYTES)
#define O_MBV (5 * TILE_BYTES + 8)
#define SMEM_REQ (5 * TILE_BYTES + 16)

__global__ __launch_bounds__(256, 1) void attn_kernel(const float* __restrict__ q,
                                                      float* __restrict__ out) {
    extern __shared__ __align__(16) uint8_t smc[];
    uint32_t sb = smem_u32(smc);

    int tid = threadIdx.x;
    int wid = tid >> 5, lane = tid & 31;
    int g = lane >> 2, t4 = lane & 3;
    int qq = lane >> 3, ii = lane & 7;
    int bx = blockIdx.x;
    int qt = 7 - (bx & 7);   // longest-job-first within scheduling order
    int h = (bx >> 3) & 15, c = (bx >> 7) & 3, b = bx >> 9;

    size_t ktb = ((size_t)((b * NH + h) * NCK + c) * 8) * TILE_BYTES;

    if (tid == 0) {
        MBAR_INIT(sb + O_MBK, 1);
        MBAR_INIT(sb + O_MBV, 1);
        // prologue (same thread: ordered after init)
        MBAR_EXPECT_TX(sb + O_MBK, 2 * TILE_BYTES);
        bulk_g2s(sb + O_KHI, g_khi + ktb, TILE_BYTES, sb + O_MBK);
        bulk_g2s(sb + O_KLO, g_klo + ktb, TILE_BYTES, sb + O_MBK);
        MBAR_EXPECT_TX(sb + O_MBV, TILE_BYTES);
        bulk_g2s(sb + O_VT, g_vt + ktb, TILE_BYTES, sb + O_MBV);
    }

    // ---- Q: load + RoPE, PRE-SCALED by log2(e), bf16 hi/lo split into SMEM
    if (tid < 128) {
        int r = tid;
        int t = c * 1024 + qt * 128 + r;
        const float4* qr = reinterpret_cast<const float4*>(q + ((size_t)(b * T + t) * NH + h) * DH);
        const float4* cr = reinterpret_cast<const float4*>(g_cos + t * HALFD);
        const float4* sr = reinterpret_cast<const float4*>(g_sin + t * HALFD);
        uint8_t* qhi = smc + O_QHI;
        uint8_t* qlo = smc + O_QLO;
#pragma unroll
        for (int i = 0; i < 16; ++i) {
            float4 x1 = qr[i], x2 = qr[i + 16], cc = cr[i], ss = sr[i];
            float4 r1 = make_float4((x1.x * cc.x - x2.x * ss.x) * LOG2E,
                                    (x1.y * cc.y - x2.y * ss.y) * LOG2E,
                                    (x1.z * cc.z - x2.z * ss.z) * LOG2E,
                                    (x1.w * cc.w - x2.w * ss.w) * LOG2E);
            float4 r2 = make_float4((x2.x * cc.x + x1.x * ss.x) * LOG2E,
                                    (x2.y * cc.y + x1.y * ss.y) * LOG2E,
                                    (x2.z * cc.z + x1.z * ss.z) * LOG2E,
                                    (x2.w * cc.w + x1.w * ss.w) * LOG2E);
            split_store(qhi, qlo, r, 4 * i, r1);
            split_store(qhi, qlo, r, 64 + 4 * i, r2);
        }
    }
    __syncthreads();   // Q ready for all warps

    // ldmatrix lane offsets
    uint32_t offA = (uint32_t)((ii + (qq & 1) * 8) * ROWSTRIDE + ((qq >> 1) * 8) * 2);
    uint32_t offB = (uint32_t)((ii + (qq >> 1) * 8) * ROWSTRIDE + ((qq & 1) * 8) * 2);
    uint32_t aQhi = sb + O_QHI + (uint32_t)(wid * 16 * ROWSTRIDE) + offA;
    uint32_t aQlo = sb + O_QLO + (uint32_t)(wid * 16 * ROWSTRIDE) + offA;
    uint32_t aKhi = sb + O_KHI + offB;
    uint32_t aKlo = sb + O_KLO + offB;
    uint32_t aVt  = sb + O_VT  + offB;

    float oc[16][4];
#pragma unroll
    for (int jn = 0; jn < 16; ++jn)
#pragma unroll
        for (int e = 0; e < 4; ++e) oc[jn][e] = 0.f;
    float m0 = -INFINITY, m1 = -INFINITY, l0 = 0.f, l1 = 0.f;
    uint32_t pk = 0, pv = 0;

    for (int j = 0; j <= qt; ++j) {
        mbar_wait(sb + O_MBK, pk);
        pk ^= 1;

        // ---- S' = (Q*log2e)*K : scores in log2 units
        float sc[16][4];
#pragma unroll
        for (int jn = 0; jn < 16; ++jn)
#pragma unroll
            for (int e = 0; e < 4; ++e) sc[jn][e] = 0.f;

#pragma unroll
        for (int kc = 0; kc < 8; ++kc) {
            uint32_t qh[4], qlr[4];
            ldsm4(qh, aQhi + kc * 32);
            ldsm4(qlr, aQlo + kc * 32);
#pragma unroll
            for (int jp = 0; jp < 8; ++jp) {
                uint32_t bh[4], bl[4];
                ldsm4(bh, aKhi + (uint32_t)(jp * 16 * ROWSTRIDE) + kc * 32);
                ldsm4(bl, aKlo + (uint32_t)(jp * 16 * ROWSTRIDE) + kc * 32);
                mma_bf16(sc[2 * jp],     qh,  bh[0], bh[1]);
                mma_bf16(sc[2 * jp + 1], qh,  bh[2], bh[3]);
                mma_bf16(sc[2 * jp],     qh,  bl[0], bl[1]);
                mma_bf16(sc[2 * jp + 1], qh,  bl[2], bl[3]);
                mma_bf16(sc[2 * jp],     qlr, bh[0], bh[1]);
                mma_bf16(sc[2 * jp + 1], qlr, bh[2], bh[3]);
            }
        }

        // K(j) consumed: 7 warps fire-and-forget; warp 0 waits + refills K
        if (j < qt) {
            if (wid == 0) {
                BAR_SYNC(4);
                if (elect_one()) {
                    MBAR_EXPECT_TX(sb + O_MBK, 2 * TILE_BYTES);
                    bulk_g2s(sb + O_KHI, g_khi + ktb + (size_t)(j + 1) * TILE_BYTES, TILE_BYTES, sb + O_MBK);
                    bulk_g2s(sb + O_KLO, g_klo + ktb + (size_t)(j + 1) * TILE_BYTES, TILE_BYTES, sb + O_MBK);
                }
            } else {
                BAR_ARRIVE(4);
            }
        }

        // ---- causal mask on diagonal tile
        if (j == qt) {
            int row0 = wid * 16 + g, row1 = row0 + 8;
#pragma unroll
            for (int jn = 0; jn < 16; ++jn) {
                int col = 8 * jn + 2 * t4;
                if (col > row0) sc[jn][0] = NEGBIG;
                if (col + 1 > row0) sc[jn][1] = NEGBIG;
                if (col > row1) sc[jn][2] = NEGBIG;
                if (col + 1 > row1) sc[jn][3] = NEGBIG;
            }
        }

        // ---- row max (4 parallel chains) + alpha
        float mx0a = -INFINITY, mx0b = -INFINITY, mx1a = -INFINITY, mx1b = -INFINITY;
#pragma unroll
        for (int jn = 0; jn < 16; jn += 2) {
            mx0a = fmaxf(mx0a, fmaxf(sc[jn][0], sc[jn][1]));
            mx1a = fmaxf(mx1a, fmaxf(sc[jn][2], sc[jn][3]));
            mx0b = fmaxf(mx0b, fmaxf(sc[jn + 1][0], sc[jn + 1][1]));
            mx1b = fmaxf(mx1b, fmaxf(sc[jn + 1][2], sc[jn + 1][3]));
        }
        float mx0 = fmaxf(mx0a, mx0b), mx1 = fmaxf(mx1a, mx1b);
        mx0 = fmaxf(mx0, __shfl_xor_sync(0xffffffffu, mx0, 1));
        mx0 = fmaxf(mx0, __shfl_xor_sync(0xffffffffu, mx0, 2));
        mx1 = fmaxf(mx1, __shfl_xor_sync(0xffffffffu, mx1, 1));
        mx1 = fmaxf(mx1, __shfl_xor_sync(0xffffffffu, mx1, 2));
        float mn0 = fmaxf(m0, mx0), mn1 = fmaxf(m1, mx1);
        float al0 = ex2(m0 - mn0), al1 = ex2(m1 - mn1);
        m0 = mn0; m1 = mn1;
        l0 *= al0; l1 *= al1;

        // ---- P = 2^(s'-m') via paired f16 ex2 (direct fp16 MMA fragments)
        uint32_t pp[32];
#pragma unroll
        for (int jn = 0; jn < 16; ++jn) {
            pp[2 * jn]     = h2ex2(f2h2(sc[jn][0] - mn0, sc[jn][1] - mn0));
            pp[2 * jn + 1] = h2ex2(f2h2(sc[jn][2] - mn1, sc[jn][3] - mn1));
            oc[jn][0] *= al0; oc[jn][1] *= al0;
            oc[jn][2] *= al1; oc[jn][3] *= al1;
        }

        mbar_wait(sb + O_MBV, pv);
        pv ^= 1;

        // ---- O += P16 * V^T ; l summed from the same f16 P values
        float s0 = 0.f, s1 = 0.f;
#pragma unroll
        for (int kc = 0; kc < 8; ++kc) {
            const uint32_t* pa = pp + 4 * kc;
            {
                float2 f0 = __half22float2(*reinterpret_cast<const __half2*>(pa + 0));
                float2 f1 = __half22float2(*reinterpret_cast<const __half2*>(pa + 1));
                float2 f2 = __half22float2(*reinterpret_cast<const __half2*>(pa + 2));
                float2 f3 = __half22float2(*reinterpret_cast<const __half2*>(pa + 3));
                s0 += f0.x + f0.y + f2.x + f2.y;
                s1 += f1.x + f1.y + f3.x + f3.y;
            }
#pragma unroll
            for (int jp = 0; jp < 8; ++jp) {
                uint32_t bv[4];
                ldsm4(bv, aVt + (uint32_t)(jp * 16 * ROWSTRIDE) + kc * 32);
                mma_f16(oc[2 * jp], pa, bv[0], bv[1]);
                mma_f16(oc[2 * jp + 1], pa, bv[2], bv[3]);
            }
        }
        s0 += __shfl_xor_sync(0xffffffffu, s0, 1);
        s0 += __shfl_xor_sync(0xffffffffu, s0, 2);
        s1 += __shfl_xor_sync(0xffffffffu, s1, 1);
        s1 += __shfl_xor_sync(0xffffffffu, s1, 2);
        l0 += s0; l1 += s1;

        // V(j) consumed: 7 warps fire-and-forget; warp 7 waits + refills V
        if (j < qt) {
            if (wid == 7) {
                BAR_SYNC(5);
                if (elect_one()) {
                    MBAR_EXPECT_TX(sb + O_MBV, TILE_BYTES);
                    bulk_g2s(sb + O_VT, g_vt + ktb + (size_t)(j + 1) * TILE_BYTES, TILE_BYTES, sb + O_MBV);
                }
            } else {
                BAR_ARRIVE(5);
            }
        }
    }

    // ---- epilogue: O / l -> gmem
    float inv0 = 1.0f / l0, inv1 = 1.0f / l1;
    int t0g = c * 1024 + qt * 128 + wid * 16 + g;
    float* o0 = out + ((size_t)(b * T + t0g) * NH + h) * DV;
    float* o1 = out + ((size_t)(b * T + t0g + 8) * NH + h) * DV;
#pragma unroll
    for (int jn = 0; jn < 16; ++jn) {
        int dv = 8 * jn + 2 * t4;
        *reinterpret_cast<float2*>(o0 + dv) = make_float2(oc[jn][0] * inv0, oc[jn][1] * inv0);
        *reinterpret_cast<float2*>(o1 + dv) = make_float2(oc[jn][2] * inv1, oc[jn][3] * inv1);
    }
}

// ---------------- launch -----------------------------------------------------
extern "C" void kernel_launch(void* const* d_in, const int* in_sizes, int n_in,
                              void* d_out, int out_size) {
    const float* q = (const float*)d_in[0];
    const float* k = (const float*)d_in[1];
    const float* v = (const float*)d_in[2];
    const int* start = (const int*)d_in[3];
    float* out = (float*)d_out;

    cudaFuncSetAttribute(attn_kernel, cudaFuncAttributeMaxDynamicSharedMemorySize, SMEM_REQ);

    tables_kernel<<<(T * HALFD + 255) / 256, 256>>>(start);
    kprep_kernel<<<NTILES, 256>>>(k);
    vprep_kernel<<<NTILES, 256>>>(v);
    attn_kernel<<<NB * NH * NCK * 8, 256, SMEM_REQ>>>(q, out);
}